// round 10
// baseline (speedup 1.0000x reference)
#include <cuda_runtime.h>
#include <math.h>
#include <stdint.h>

#define O_   16
#define C_   64
#define NN   576
#define LL   1024
#define B_   8
#define CH   64
#define NCH  9
#define EPSN 1e-4f
#define WP2  70        // float2 pitch per o row in wb (64 + 6 pad -> conflict-free)

// Persistent scratch (no cudaMalloc). g_A rewritten bit-identically each launch;
// stale flags on graph replay are benign (idempotent writes).
__device__ float g_A[O_ * 81];
__device__ int   g_Aflag[O_];

// ---- smem float offsets ---------------------------------------------------
#define US_OFF 0        // [2][2048]
#define YB_OFF 4096     // [3][2048]
#define NB_OFF 10240    // [3][2048]
#define WB_OFF 16384    // [4][2240]  (16 o x 70 fl2 per buf)
#define Z0_OFF 25344
#define S2_OFF 25376
#define P1_OFF 25408    // [32][33] -> 1088
#define P2_OFF 26496    // 1088
#define SM_FLOATS 27584 // 110336 B

// ---------------------------------------------------------------------------
#define FMA2(acc_, x_, u_) \
    asm("fma.rn.f32x2 %0, %1, %2, %0;" : "+l"(acc_) : "l"(x_), "l"(u_))
#define MUL2(d_, a_, b_) \
    asm("mul.rn.f32x2 %0, %1, %2;" : "=l"(d_) : "l"(a_), "l"(b_))

__device__ __forceinline__ unsigned long long pk2(float a, float b) {
    unsigned long long r;
    asm("mov.b64 %0, {%1, %2};"
        : "=l"(r) : "r"(__float_as_uint(a)), "r"(__float_as_uint(b)));
    return r;
}
__device__ __forceinline__ void cp16(unsigned dst, const void* src) {
    asm volatile("cp.async.cg.shared.global [%0], [%1], 16;" :: "r"(dst), "l"(src));
}
__device__ __forceinline__ void cp4z(unsigned dst, const void* src, int pred) {
    asm volatile("cp.async.ca.shared.global [%0], [%1], 4, %2;"
                 :: "r"(dst), "l"(src), "r"(pred ? 4 : 0));
}
#define CP_COMMIT() asm volatile("cp.async.commit_group;")
#define CP_WAIT1()  asm volatile("cp.async.wait_group 1;")

// ---------------------------------------------------------------------------
// Blocks 0..15: fp32 symmetric-scaled inverse covariance for channel o.
// Powers regenerated on the fly -> only 560 floats of scratch (us region,
// used strictly before the main loop's first combine).
// ---------------------------------------------------------------------------
__device__ void build_A_o(const float* __restrict__ wgt, float* S, int o, int t) {
    float* parts = S;        // 243
    float* Cf    = S + 256;  // 81
    float* Cm    = S + 352;  // 171
    float* Dv    = S + 528;  // 9
    float* fv    = S + 544;  // 9

    if (t < 243) {
        int pair = t / 3, sl = t - pair * 3;
        int p = pair / 9, q = pair - (pair / 9) * 9;
        int dp = (p + 1) >> 1, sp = p ? ((p - 1) & 1) : 0;
        int dq = (q + 1) >> 1, sq = q ? ((q - 1) & 1) : 0;
        float s = 0.0f;
        for (int n = sl * 192; n < sl * 192 + 192; n++) {
            const float* wn = wgt + (o * NN + n) * 2;
            float a = 1.0f, bq = 1.0f;
            if (p) { float w = wn[sp]; a = w;  for (int d = 1; d < dp; d++) a  *= w; }
            if (q) { float w = wn[sq]; bq = w; for (int d = 1; d < dq; d++) bq *= w; }
            s += a * bq;
        }
        parts[t] = s;
    }
    __syncthreads();
    if (t < 81) Cf[t] = parts[3 * t] + parts[3 * t + 1] + parts[3 * t + 2];
    __syncthreads();
    if (t < 9) Dv[t] = rsqrtf(Cf[t * 9 + t]);
    __syncthreads();
    if (t < 81) {
        int p = t / 9, q = t - 9 * (t / 9);
        Cm[p * 19 + q]     = Cf[t] * Dv[p] * Dv[q];
        Cm[p * 19 + 9 + q] = (p == q) ? 1.0f : 0.0f;
    }
    __syncthreads();
    for (int k = 0; k < 9; k++) {
        if (t < 9) fv[t] = Cm[t * 19 + k];
        __syncthreads();
        if (t < 19) Cm[k * 19 + t] *= (1.0f / fv[k]);
        __syncthreads();
        if (t < 171) {
            int ii = t / 19, jj = t - 19 * (t / 19);
            if (ii != k) Cm[ii * 19 + jj] -= fv[ii] * Cm[k * 19 + jj];
        }
        __syncthreads();
    }
    if (t < 81) {
        int p = t / 9, q = t - 9 * (t / 9);
        g_A[o * 81 + t] = Dv[p] * Cm[p * 19 + 9 + q] * Dv[q];
    }
    __syncthreads();
    __threadfence();
    if (t == 0) *((volatile int*)&g_Aflag[o]) = 1;
    __syncthreads();
}

// ---------------------------------------------------------------------------
// Stage chunk cc: yb/nb cycle mod 3 (consumed pre-sync), wb mod 4 (post-sync).
// Self-ownership: thread t stages exactly the yb/nb floats it will combine.
// ---------------------------------------------------------------------------
__device__ __forceinline__ void stage_chunk(
    int cc, int t, int i, unsigned sbase,
    const float* __restrict__ y2b,
    const char*  __restrict__ nzb,
    const char*  __restrict__ wgb)
{
    int b3 = cc % 3, b4 = cc & 3;
    unsigned yb_b = sbase + (YB_OFF + b3 * 2048) * 4;
    unsigned nb_b = sbase + (NB_OFF + b3 * 2048) * 4;
    unsigned wb_b = sbase + (WB_OFF + b4 * 2240) * 4;

    #pragma unroll
    for (int g2 = 0; g2 < 2; g2++) {
        int gran = t + g2 * 256;
        cp16(nb_b + gran * 16,
             nzb + ((size_t)(cc * CH + (gran >> 3))) * (LL * 4) + (gran & 7) * 16);
    }
    #pragma unroll
    for (int g2 = 0; g2 < 2; g2++) {
        int gran = t + g2 * 256;
        int oo = gran >> 5, gi = gran & 31;
        cp16(wb_b + oo * (WP2 * 8) + gi * 16,
             wgb + ((size_t)(oo * NN + cc * CH + gi * 2)) * 8);
    }
    #pragma unroll
    for (int q = 0; q < 8; q++) {
        int k = 4 * t + (q & 3) + (q >> 2) * 1024;
        int n  = cc * CH + (k >> 5);
        int j  = k & 31;
        int ch = n / 9;
        int kk = n - ch * 9;
        int ki = kk / 3, kj = kk - ki * 3;
        int rr = i + ki - 1;
        int cl = j + kj - 1;
        int ok = ((unsigned)rr < 32u) & ((unsigned)cl < 32u);
        const float* srcp = ok ? (y2b + (ch * 32 + rr) * 32 + cl) : y2b;
        cp4z(yb_b + k * 4, srcp, ok);
    }
}

// ---------------------------------------------------------------------------
// Fused kernel. Block = (b, image row i). 256 threads:
// h = t>>6 (n-quarter, 16 n each), r = t&63, o = r>>2, g = r&3, j0 = 8g.
// Each thread: 8 j x 8 p via 32 f32x2 accumulators. ONE barrier per chunk.
// ---------------------------------------------------------------------------
__global__ void __launch_bounds__(256, 2) srn_main(
    const float* __restrict__ y2,
    const float* __restrict__ wgt,
    const float* __restrict__ noise,
    float* __restrict__ out)
{
    extern __shared__ float sm[];
    unsigned sbase = (unsigned)__cvta_generic_to_shared(sm);

    int bidx = blockIdx.x;
    int b = bidx >> 5;
    int i = bidx & 31;
    int t = threadIdx.x;
    int h = t >> 6;
    int r = t & 63;
    int o = r >> 2;
    int g = r & 3;
    int j0 = g * 8;

    unsigned long long acc[32];      // acc[j*4+k]: (w1^{k+1}, w2^{k+1}) sums for j0+j
    #pragma unroll
    for (int k = 0; k < 32; k++) acc[k] = 0ULL;
    float sa1[4] = {0, 0, 0, 0};
    float sa2[4] = {0, 0, 0, 0};

    const float* y2b = y2 + b * (C_ * 32 * 32);
    const char*  nzb = (const char*)(noise + (size_t)b * (NN * LL) + (size_t)i * 32);
    const char*  wgb = (const char*)wgt;

    // builders first (uses us region as scratch; staging not yet issued)
    if (bidx < O_)
        build_A_o(wgt, sm, bidx, t);

    stage_chunk(0, t, i, sbase, y2b, nzb, wgb);
    CP_COMMIT();
    stage_chunk(1, t, i, sbase, y2b, nzb, wgb);
    CP_COMMIT();

    for (int c = 0; c < NCH; c++) {
        int b3 = c % 3;
        int b2 = c & 1;
        CP_WAIT1();                 // stage(c) landed (c+1 may be in flight)

        // ---- combine own floats ----
        #pragma unroll
        for (int hf = 0; hf < 2; hf++) {
            int kb = 4 * t + hf * 1024;
            float4 yv = *(const float4*)(sm + YB_OFF + b3 * 2048 + kb);
            float4 nv = *(const float4*)(sm + NB_OFF + b3 * 2048 + kb);
            float v0 = fmaf(EPSN, nv.x, yv.x);
            float v1 = fmaf(EPSN, nv.y, yv.y);
            float v2 = fmaf(EPSN, nv.z, yv.z);
            float v3 = fmaf(EPSN, nv.w, yv.w);
            sa1[0] += v0; sa2[0] += v0 * v0;
            sa1[1] += v1; sa2[1] += v1 * v1;
            sa1[2] += v2; sa2[2] += v2 * v2;
            sa1[3] += v3; sa2[3] += v3 * v3;
            *(float4*)(sm + US_OFF + b2 * 2048 + kb) = make_float4(v0, v1, v2, v3);
        }

        if (c + 2 < NCH)
            stage_chunk(c + 2, t, i, sbase, y2b, nzb, wgb);
        CP_COMMIT();                // one group per iteration (may be empty)
        __syncthreads();            // us[b2] + wb[c&3] visible to all

        // ---- compute over this thread's n-quarter (16 n) ----
        const float* up = sm + US_OFF + b2 * 2048 + h * 512;
        const float2* wp = (const float2*)(sm + WB_OFF) + (c & 3) * 1120 + o * WP2 + h * 16;
        #pragma unroll 2
        for (int nl = 0; nl < 16; nl++) {
            float4 ua = *(const float4*)(up + nl * 32 + j0);
            float4 ub = *(const float4*)(up + nl * 32 + j0 + 4);
            unsigned long long m1 = *(const unsigned long long*)(wp + nl);
            unsigned long long m2, m3, m4;
            MUL2(m2, m1, m1);
            MUL2(m3, m2, m1);
            MUL2(m4, m2, m2);
            unsigned long long s0 = pk2(ua.x, ua.x), s1 = pk2(ua.y, ua.y);
            unsigned long long s2 = pk2(ua.z, ua.z), s3 = pk2(ua.w, ua.w);
            unsigned long long s4 = pk2(ub.x, ub.x), s5 = pk2(ub.y, ub.y);
            unsigned long long s6 = pk2(ub.z, ub.z), s7 = pk2(ub.w, ub.w);
            FMA2(acc[0],  m1, s0); FMA2(acc[1],  m2, s0); FMA2(acc[2],  m3, s0); FMA2(acc[3],  m4, s0);
            FMA2(acc[4],  m1, s1); FMA2(acc[5],  m2, s1); FMA2(acc[6],  m3, s1); FMA2(acc[7],  m4, s1);
            FMA2(acc[8],  m1, s2); FMA2(acc[9],  m2, s2); FMA2(acc[10], m3, s2); FMA2(acc[11], m4, s2);
            FMA2(acc[12], m1, s3); FMA2(acc[13], m2, s3); FMA2(acc[14], m3, s3); FMA2(acc[15], m4, s3);
            FMA2(acc[16], m1, s4); FMA2(acc[17], m2, s4); FMA2(acc[18], m3, s4); FMA2(acc[19], m4, s4);
            FMA2(acc[20], m1, s5); FMA2(acc[21], m2, s5); FMA2(acc[22], m3, s5); FMA2(acc[23], m4, s5);
            FMA2(acc[24], m1, s6); FMA2(acc[25], m2, s6); FMA2(acc[26], m3, s6); FMA2(acc[27], m4, s6);
            FMA2(acc[28], m1, s7); FMA2(acc[29], m2, s7); FMA2(acc[30], m3, s7); FMA2(acc[31], m4, s7);
        }
        // no end-of-iteration barrier: us double-buffered (reuse distance 2),
        // yb/nb consumed pre-sync (3 bufs), wb consumed post-sync (4 bufs).
    }

    __syncthreads();    // all compute done before overlaying scratch

    // ---- phase A: stats partials + acc partials ----
    {
        int slot = t >> 3;
        #pragma unroll
        for (int q = 0; q < 4; q++) {
            int jq = 4 * (t & 7) + q;
            sm[P1_OFF + jq * 33 + slot] = sa1[q];
            sm[P2_OFF + jq * 33 + slot] = sa2[q];
        }
    }
    if (h) {
        float* base = sm + (h - 1) * 4352 + r * 68;   // overlays us/yb/nb
        #pragma unroll
        for (int m = 0; m < 32; m++)
            *(unsigned long long*)(base + 2 * m) = acc[m];
    }
    __syncthreads();

    // ---- phase B: stats reduce (warps 2..2) + quarter merge + Wm (h==0) ----
    if (t >= 64 && t < 96) {
        int j = t - 64;
        float a = 0.0f, bb = 0.0f;
        #pragma unroll
        for (int s = 0; s < 32; s++) {
            a  += sm[P1_OFF + j * 33 + s];
            bb += sm[P2_OFF + j * 33 + s];
        }
        sm[Z0_OFF + j] = a;
        sm[S2_OFF + j] = bb;
    }
    if (h == 0) {
        float f[64];
        #pragma unroll
        for (int m = 0; m < 32; m++) {
            f[2 * m]     = __uint_as_float((unsigned)acc[m]);
            f[2 * m + 1] = __uint_as_float((unsigned)(acc[m] >> 32));
        }
        #pragma unroll
        for (int q3 = 0; q3 < 3; q3++) {
            const float* s = sm + q3 * 4352 + r * 68;
            #pragma unroll
            for (int x = 0; x < 64; x++) f[x] += s[x];
        }
        float* Wm = sm + WB_OFF;   // [128 rows][33], overlays wb (drained)
        #pragma unroll
        for (int j = 0; j < 8; j++)
            #pragma unroll
            for (int k = 0; k < 4; k++) {
                Wm[(o * 8 + 2 * k)     * 33 + (j0 + j)] = f[(j * 4 + k) * 2];
                Wm[(o * 8 + 2 * k + 1) * 33 + (j0 + j)] = f[(j * 4 + k) * 2 + 1];
            }
    }
    __syncthreads();

    // ---- phase C: epilogue, 2 (o,j) outputs per thread ----
    const float* Wm = sm + WB_OFF;
    #pragma unroll
    for (int rep = 0; rep < 2; rep++) {
        int e = t + rep * 256;
        int oo = e >> 5;
        int j = e & 31;
        while (*((volatile int*)&g_Aflag[oo]) == 0) {}
        __threadfence();
        float wv[9];
        wv[0] = sm[Z0_OFF + j];
        #pragma unroll
        for (int p = 1; p <= 8; p++)
            wv[p] = Wm[(oo * 8 + p - 1) * 33 + j];
        const float* A = g_A + oo * 81;
        float wAw = 0.0f;
        #pragma unroll
        for (int p = 0; p < 9; p++) {
            float tp = 0.0f;
            #pragma unroll
            for (int q = 0; q < 9; q++)
                tp = fmaf(__ldg(&A[p * 9 + q]), wv[q], tp);
            wAw = fmaf(tp, wv[p], wAw);
        }
        float S2 = sm[S2_OFF + j];
        float z0 = wv[0];
        float denom = S2 - z0 * z0 * (1.0f / 576.0f);
        float err = (S2 - wAw) * (575.0f / 576.0f) / denom;
        out[((size_t)(b * 16 + oo)) * 1024 + i * 32 + j] = expf(-err);
    }
}

// ---------------------------------------------------------------------------
extern "C" void kernel_launch(void* const* d_in, const int* in_sizes, int n_in,
                              void* d_out, int out_size) {
    const float* y2 = nullptr;
    const float* w  = nullptr;
    const float* nz = nullptr;
    for (int k = 0; k < n_in; k++) {
        if      (in_sizes[k] == 524288)  y2 = (const float*)d_in[k];
        else if (in_sizes[k] == 18432)   w  = (const float*)d_in[k];
        else if (in_sizes[k] == 4718592) nz = (const float*)d_in[k];
    }
    if (!y2 || !w || !nz) {
        y2 = (const float*)d_in[0];
        w  = (const float*)d_in[1];
        nz = (const float*)d_in[2];
    }

    const int smem_bytes = SM_FLOATS * 4;   // 110336 B
    cudaFuncSetAttribute(srn_main, cudaFuncAttributeMaxDynamicSharedMemorySize, smem_bytes);
    srn_main<<<B_ * 32, 256, smem_bytes>>>(y2, w, nz, (float*)d_out);
}

// round 11
// speedup vs baseline: 1.0753x; 1.0753x over previous
#include <cuda_runtime.h>
#include <math.h>
#include <stdint.h>

#define O_   16
#define C_   64
#define NN   576
#define LL   1024
#define B_   8
#define CH   64
#define NCH  9
#define EPSN 1e-4f
#define WP2  68        // float2 pitch per o row in wb (136 fl -> 8-bank offset/o)

// Persistent scratch (no cudaMalloc). g_A rewritten bit-identically each
// launch; stale flags on graph replay are benign (idempotent writes).
__device__ float g_A[O_ * 81];
__device__ int   g_Aflag[O_];

// ---- smem float offsets ---------------------------------------------------
#define US_OFF 0        // [2][2048]
#define NB_OFF 4096     // [3][2048]  (acc scratch stride-34 after loop)
#define WB_OFF 10240    // [4][2176]  (16 o x 68 fl2 per buf)
#define Z0_OFF 18944
#define S2_OFF 18976
#define P1_OFF 19008    // [32][33] padded -> 1088
#define P2_OFF 20096    // 1088
#define SM_FLOATS 21184 // 84736 B

// ---------------------------------------------------------------------------
#define FMA2(acc_, x_, u_) \
    asm("fma.rn.f32x2 %0, %1, %2, %0;" : "+l"(acc_) : "l"(x_), "l"(u_))
#define MUL2(d_, a_, b_) \
    asm("mul.rn.f32x2 %0, %1, %2;" : "=l"(d_) : "l"(a_), "l"(b_))

__device__ __forceinline__ unsigned long long pk2(float a, float b) {
    unsigned long long r;
    asm("mov.b64 %0, {%1, %2};"
        : "=l"(r) : "r"(__float_as_uint(a)), "r"(__float_as_uint(b)));
    return r;
}
__device__ __forceinline__ void cp16(unsigned dst, const void* src) {
    asm volatile("cp.async.cg.shared.global [%0], [%1], 16;" :: "r"(dst), "l"(src));
}
#define CP_COMMIT() asm volatile("cp.async.commit_group;")
#define CP_WAIT1()  asm volatile("cp.async.wait_group 1;")

// ---------------------------------------------------------------------------
// Blocks 0..15: fp32 symmetric-scaled inverse covariance for channel o.
// Powers regenerated on the fly -> 560 floats of scratch (US region, used
// strictly before the first combine writes us).
// ---------------------------------------------------------------------------
__device__ void build_A_o(const float* __restrict__ wgt, float* S, int o, int t) {
    float* parts = S;        // 243
    float* Cf    = S + 256;  // 81
    float* Cm    = S + 352;  // 171
    float* Dv    = S + 528;  // 9
    float* fv    = S + 544;  // 9

    if (t < 243) {
        int pair = t / 3, sl = t - pair * 3;
        int p = pair / 9, q = pair - (pair / 9) * 9;
        int dp = (p + 1) >> 1, sp = p ? ((p - 1) & 1) : 0;
        int dq = (q + 1) >> 1, sq = q ? ((q - 1) & 1) : 0;
        float s = 0.0f;
        for (int n = sl * 192; n < sl * 192 + 192; n++) {
            const float* wn = wgt + (o * NN + n) * 2;
            float a = 1.0f, bq = 1.0f;
            if (p) { float w = wn[sp]; a = w;  for (int d = 1; d < dp; d++) a  *= w; }
            if (q) { float w = wn[sq]; bq = w; for (int d = 1; d < dq; d++) bq *= w; }
            s += a * bq;
        }
        parts[t] = s;
    }
    __syncthreads();
    if (t < 81) Cf[t] = parts[3 * t] + parts[3 * t + 1] + parts[3 * t + 2];
    __syncthreads();
    if (t < 9) Dv[t] = rsqrtf(Cf[t * 9 + t]);
    __syncthreads();
    if (t < 81) {
        int p = t / 9, q = t - 9 * (t / 9);
        Cm[p * 19 + q]     = Cf[t] * Dv[p] * Dv[q];
        Cm[p * 19 + 9 + q] = (p == q) ? 1.0f : 0.0f;
    }
    __syncthreads();
    for (int k = 0; k < 9; k++) {
        if (t < 9) fv[t] = Cm[t * 19 + k];
        __syncthreads();
        if (t < 19) Cm[k * 19 + t] *= (1.0f / fv[k]);
        __syncthreads();
        if (t < 171) {
            int ii = t / 19, jj = t - 19 * (t / 19);
            if (ii != k) Cm[ii * 19 + jj] -= fv[ii] * Cm[k * 19 + jj];
        }
        __syncthreads();
    }
    if (t < 81) {
        int p = t / 9, q = t - 9 * (t / 9);
        g_A[o * 81 + t] = Dv[p] * Cm[p * 19 + 9 + q] * Dv[q];
    }
    __syncthreads();
    __threadfence();
    if (t == 0) *((volatile int*)&g_Aflag[o]) = 1;
    __syncthreads();
}

// ---------------------------------------------------------------------------
// Stage chunk cc: noise -> NB[cc%3], weights -> WB[cc%4]. Self-ownership:
// thread t stages exactly the NB floats it will combine (4t..4t+3, +1024).
// ---------------------------------------------------------------------------
__device__ __forceinline__ void stage_chunk(
    int cc, int t, unsigned sbase,
    const char* __restrict__ nzb,
    const char* __restrict__ wgb)
{
    unsigned nb_b = sbase + (NB_OFF + (cc % 3) * 2048) * 4;
    unsigned wb_b = sbase + (WB_OFF + (cc & 3) * 2176) * 4;

    #pragma unroll
    for (int g2 = 0; g2 < 2; g2++) {
        int gran = t + g2 * 256;
        cp16(nb_b + gran * 16,
             nzb + ((size_t)(cc * CH + (gran >> 3))) * (LL * 4) + (gran & 7) * 16);
    }
    #pragma unroll
    for (int g2 = 0; g2 < 2; g2++) {
        int gran = t + g2 * 256;
        int oo = gran >> 5, gi = gran & 31;
        cp16(wb_b + oo * (WP2 * 8) + gi * 16,
             wgb + ((size_t)(oo * NN + cc * CH + gi * 2)) * 8);
    }
}

// ---------------------------------------------------------------------------
// Fused kernel. Block = (b, image row i). 256 threads:
// h = t>>7 (n-half, 32 n), r = t&127, o = r>>3, g = r&7, j0 = 4g.
// 16 f32x2 accumulators (R8 core). ONE barrier per chunk.
// ---------------------------------------------------------------------------
__global__ void __launch_bounds__(256, 2) srn_main(
    const float* __restrict__ y2,
    const float* __restrict__ wgt,
    const float* __restrict__ noise,
    float* __restrict__ out)
{
    extern __shared__ float sm[];
    unsigned sbase = (unsigned)__cvta_generic_to_shared(sm);

    int bidx = blockIdx.x;
    int b = bidx >> 5;
    int i = bidx & 31;
    int t = threadIdx.x;
    int h = t >> 7;
    int r = t & 127;
    int o = r >> 3;
    int g = r & 7;
    int j0 = g * 4;

    unsigned long long acc[16];
    #pragma unroll
    for (int k = 0; k < 16; k++) acc[k] = 0ULL;
    float sa1[4] = {0, 0, 0, 0};
    float sa2[4] = {0, 0, 0, 0};

    const float* y2b = y2 + b * (C_ * 32 * 32);
    const char*  nzb = (const char*)(noise + (size_t)b * (NN * LL) + (size_t)i * 32);
    const char*  wgb = (const char*)wgt;

    stage_chunk(0, t, sbase, nzb, wgb);
    CP_COMMIT();
    stage_chunk(1, t, sbase, nzb, wgb);
    CP_COMMIT();

    // builders overlap the in-flight staging DRAM
    if (bidx < O_)
        build_A_o(wgt, sm, bidx, t);

    for (int c = 0; c < NCH; c++) {
        int b3 = c % 3;
        int b2 = c & 1;
        CP_WAIT1();                 // stage(c) landed (c+1 may be in flight)

        // ---- combine: u = y2(unfold, via L2-resident LDG) + eps*noise ----
        #pragma unroll
        for (int hf = 0; hf < 2; hf++) {
            int k0 = 4 * t + hf * 1024;
            int nl = k0 >> 5;              // n within chunk (fixed per hf)
            int jb = k0 & 31;              // = 4*(t&7)
            int n  = c * CH + nl;
            int ch = n / 9;
            int kk = n - ch * 9;
            int ki = kk / 3, kj = kk - ki * 3;
            int rr = i + ki - 1;
            int rowok = ((unsigned)rr < 32u);
            const float* rowp = y2b + (ch * 32 + rr) * 32;
            float4 nv = *(const float4*)(sm + NB_OFF + b3 * 2048 + k0);
            float vq[4];
            #pragma unroll
            for (int q = 0; q < 4; q++) {
                int cl = jb + q + kj - 1;
                float yv = 0.0f;
                if (rowok & ((unsigned)cl < 32u)) yv = __ldg(rowp + cl);
                float u = fmaf(EPSN, ((const float*)&nv)[q], yv);
                vq[q] = u;
                sa1[q] += u;
                sa2[q] += u * u;
            }
            *(float4*)(sm + US_OFF + b2 * 2048 + k0) =
                make_float4(vq[0], vq[1], vq[2], vq[3]);
        }

        if (c + 2 < NCH)
            stage_chunk(c + 2, t, sbase, nzb, wgb);
        CP_COMMIT();                // one group per iteration (may be empty)
        __syncthreads();            // us[b2] + wb[c&3] visible to all

        // ---- compute over this thread's n-half (32 n) ----
        const float*  up = sm + US_OFF + b2 * 2048 + h * 1024;
        const float2* wp = (const float2*)(sm + WB_OFF) + (c & 3) * 1088 + o * WP2 + h * 32;
        #pragma unroll 4
        for (int nl = 0; nl < 32; nl++) {
            float4 uu = *(const float4*)(up + nl * 32 + j0);
            unsigned long long m1 = *(const unsigned long long*)(wp + nl);
            unsigned long long m2, m3, m4;
            MUL2(m2, m1, m1);
            MUL2(m3, m2, m1);
            MUL2(m4, m2, m2);
            unsigned long long ua = pk2(uu.x, uu.x);
            unsigned long long ub = pk2(uu.y, uu.y);
            unsigned long long uc = pk2(uu.z, uu.z);
            unsigned long long ud = pk2(uu.w, uu.w);
            FMA2(acc[0],  m1, ua); FMA2(acc[1],  m2, ua);
            FMA2(acc[2],  m3, ua); FMA2(acc[3],  m4, ua);
            FMA2(acc[4],  m1, ub); FMA2(acc[5],  m2, ub);
            FMA2(acc[6],  m3, ub); FMA2(acc[7],  m4, ub);
            FMA2(acc[8],  m1, uc); FMA2(acc[9],  m2, uc);
            FMA2(acc[10], m3, uc); FMA2(acc[11], m4, uc);
            FMA2(acc[12], m1, ud); FMA2(acc[13], m2, ud);
            FMA2(acc[14], m3, ud); FMA2(acc[15], m4, ud);
        }
        // no end-of-iteration barrier: us mod-2 (reuse distance 2), nb mod-3
        // consumed pre-sync, wb mod-4 consumed post-sync.
    }

    __syncthreads();    // all compute done before overlaying scratch

    // ---- stats partials (stride 33) + acc partials (stride 34, NB region) --
    {
        int slot = t >> 3;
        #pragma unroll
        for (int q = 0; q < 4; q++) {
            int jq = 4 * (t & 7) + q;
            sm[P1_OFF + jq * 33 + slot] = sa1[q];
            sm[P2_OFF + jq * 33 + slot] = sa2[q];
        }
    }
    if (h == 1) {
        float* base = sm + NB_OFF + r * 34;
        #pragma unroll
        for (int k = 0; k < 16; k++)
            *(unsigned long long*)(base + 2 * k) = acc[k];
    }
    __syncthreads();

    if (t < 32) {
        float a = 0.0f, bb = 0.0f;
        #pragma unroll
        for (int s = 0; s < 32; s++) {
            a  += sm[P1_OFF + t * 33 + s];
            bb += sm[P2_OFF + t * 33 + s];
        }
        sm[Z0_OFF + t] = a;
        sm[S2_OFF + t] = bb;
    }
    __syncthreads();

    // ---- epilogue: h==0 threads own (o, j0..j0+3) ----
    if (h == 0) {
        const float* base = sm + NB_OFF + r * 34;
        float wv[4][8];
        #pragma unroll
        for (int loc = 0; loc < 4; loc++)
            #pragma unroll
            for (int pp = 0; pp < 4; pp++) {
                unsigned long long a = acc[loc * 4 + pp];
                int k = loc * 4 + pp;
                wv[loc][2 * pp]     = __uint_as_float((unsigned)a)         + base[2 * k];
                wv[loc][2 * pp + 1] = __uint_as_float((unsigned)(a >> 32)) + base[2 * k + 1];
            }

        while (*((volatile int*)&g_Aflag[o]) == 0) {}
        __threadfence();

        float w0v[4], wAw[4];
        #pragma unroll
        for (int loc = 0; loc < 4; loc++) {
            w0v[loc] = sm[Z0_OFF + j0 + loc];
            wAw[loc] = 0.0f;
        }
        const float* A = g_A + o * 81;
        #pragma unroll
        for (int p = 0; p < 9; p++) {
            float tp[4] = {0.0f, 0.0f, 0.0f, 0.0f};
            #pragma unroll
            for (int q = 0; q < 9; q++) {
                float a = __ldg(&A[p * 9 + q]);
                #pragma unroll
                for (int loc = 0; loc < 4; loc++) {
                    float v = (q == 0) ? w0v[loc] : wv[loc][q - 1];
                    tp[loc] = fmaf(a, v, tp[loc]);
                }
            }
            #pragma unroll
            for (int loc = 0; loc < 4; loc++) {
                float v = (p == 0) ? w0v[loc] : wv[loc][p - 1];
                wAw[loc] = fmaf(tp[loc], v, wAw[loc]);
            }
        }

        float4 res;
        #pragma unroll
        for (int loc = 0; loc < 4; loc++) {
            float S2 = sm[S2_OFF + j0 + loc];
            float z0 = w0v[loc];
            float denom = S2 - z0 * z0 * (1.0f / 576.0f);
            float err = (S2 - wAw[loc]) * (575.0f / 576.0f) / denom;
            ((float*)&res)[loc] = expf(-err);
        }
        *(float4*)(out + ((size_t)(b * 16 + o)) * 1024 + i * 32 + j0) = res;
    }
}

// ---------------------------------------------------------------------------
extern "C" void kernel_launch(void* const* d_in, const int* in_sizes, int n_in,
                              void* d_out, int out_size) {
    const float* y2 = nullptr;
    const float* w  = nullptr;
    const float* nz = nullptr;
    for (int k = 0; k < n_in; k++) {
        if      (in_sizes[k] == 524288)  y2 = (const float*)d_in[k];
        else if (in_sizes[k] == 18432)   w  = (const float*)d_in[k];
        else if (in_sizes[k] == 4718592) nz = (const float*)d_in[k];
    }
    if (!y2 || !w || !nz) {
        y2 = (const float*)d_in[0];
        w  = (const float*)d_in[1];
        nz = (const float*)d_in[2];
    }

    const int smem_bytes = SM_FLOATS * 4;   // 84736 B
    cudaFuncSetAttribute(srn_main, cudaFuncAttributeMaxDynamicSharedMemorySize, smem_bytes);
    srn_main<<<B_ * 32, 256, smem_bytes>>>(y2, w, nz, (float*)d_out);
}

// round 12
// speedup vs baseline: 1.1088x; 1.0312x over previous
#include <cuda_runtime.h>
#include <math.h>
#include <stdint.h>

#define O_   16
#define C_   64
#define NN   576
#define LL   1024
#define B_   8
#define CH   64
#define NCH  9
#define EPSN 1e-4f
#define WP2  68        // float2 pitch per o row in wb

// Persistent scratch (no cudaMalloc). g_A rewritten bit-identically each
// launch; stale flags on graph replay are benign (idempotent writes).
__device__ float g_A[O_ * 81];
__device__ int   g_Aflag[O_];

// ---- smem float offsets ---------------------------------------------------
#define US_OFF 0        // [3][2048]   (builder scratch pre-loop; P1/P2 post)
#define YB_OFF 6144     // [3][2048]   (acc-reduction scratch post-loop)
#define NB_OFF 12288    // [3][2048]
#define WB_OFF 18432    // [4][2176]
#define Z0_OFF 27136
#define S2_OFF 27168
#define SM_FLOATS 27200 // 108800 B
// post-loop overlays: P1 = sm+0 (32*33), P2 = sm+1088, accred = sm+YB_OFF (128*34)

// ---------------------------------------------------------------------------
#define FMA2(acc_, x_, u_) \
    asm("fma.rn.f32x2 %0, %1, %2, %0;" : "+l"(acc_) : "l"(x_), "l"(u_))
#define MUL2(d_, a_, b_) \
    asm("mul.rn.f32x2 %0, %1, %2;" : "=l"(d_) : "l"(a_), "l"(b_))

__device__ __forceinline__ unsigned long long pk2(float a, float b) {
    unsigned long long r;
    asm("mov.b64 %0, {%1, %2};"
        : "=l"(r) : "r"(__float_as_uint(a)), "r"(__float_as_uint(b)));
    return r;
}
__device__ __forceinline__ void cp16(unsigned dst, const void* src) {
    asm volatile("cp.async.cg.shared.global [%0], [%1], 16;" :: "r"(dst), "l"(src));
}
__device__ __forceinline__ void cp4z(unsigned dst, const void* src, int pred) {
    asm volatile("cp.async.ca.shared.global [%0], [%1], 4, %2;"
                 :: "r"(dst), "l"(src), "r"(pred ? 4 : 0));
}
#define CP_COMMIT() asm volatile("cp.async.commit_group;")
#define CP_WAIT1()  asm volatile("cp.async.wait_group 1;")

// ---------------------------------------------------------------------------
// Blocks 0..15: fp32 symmetric-scaled inverse covariance for channel o.
// __noinline__ so its register demand cannot inflate the main loop's
// allocation (the R10/R11 spill suspect). Scratch = US region (pre-loop).
// ---------------------------------------------------------------------------
__device__ __noinline__ void build_A_o(const float* __restrict__ wgt, float* S,
                                       int o, int t) {
    float* parts = S;        // 243
    float* Cf    = S + 256;  // 81
    float* Cm    = S + 352;  // 171
    float* Dv    = S + 528;  // 9
    float* fv    = S + 544;  // 9

    if (t < 243) {
        int pair = t / 3, sl = t - pair * 3;
        int p = pair / 9, q = pair - (pair / 9) * 9;
        int dp = (p + 1) >> 1, sp = p ? ((p - 1) & 1) : 0;
        int dq = (q + 1) >> 1, sq = q ? ((q - 1) & 1) : 0;
        float s = 0.0f;
        for (int n = sl * 192; n < sl * 192 + 192; n++) {
            const float* wn = wgt + (o * NN + n) * 2;
            float a = 1.0f, bq = 1.0f;
            if (p) { float w = wn[sp]; a = w;  for (int d = 1; d < dp; d++) a  *= w; }
            if (q) { float w = wn[sq]; bq = w; for (int d = 1; d < dq; d++) bq *= w; }
            s += a * bq;
        }
        parts[t] = s;
    }
    __syncthreads();
    if (t < 81) Cf[t] = parts[3 * t] + parts[3 * t + 1] + parts[3 * t + 2];
    __syncthreads();
    if (t < 9) Dv[t] = rsqrtf(Cf[t * 9 + t]);
    __syncthreads();
    if (t < 81) {
        int p = t / 9, q = t - 9 * (t / 9);
        Cm[p * 19 + q]     = Cf[t] * Dv[p] * Dv[q];
        Cm[p * 19 + 9 + q] = (p == q) ? 1.0f : 0.0f;
    }
    __syncthreads();
    for (int k = 0; k < 9; k++) {
        if (t < 9) fv[t] = Cm[t * 19 + k];
        __syncthreads();
        if (t < 19) Cm[k * 19 + t] *= (1.0f / fv[k]);
        __syncthreads();
        if (t < 171) {
            int ii = t / 19, jj = t - 19 * (t / 19);
            if (ii != k) Cm[ii * 19 + jj] -= fv[ii] * Cm[k * 19 + jj];
        }
        __syncthreads();
    }
    if (t < 81) {
        int p = t / 9, q = t - 9 * (t / 9);
        g_A[o * 81 + t] = Dv[p] * Cm[p * 19 + 9 + q] * Dv[q];
    }
    __syncthreads();
    __threadfence();
    if (t == 0) *((volatile int*)&g_Aflag[o]) = 1;
    __syncthreads();
}

// ---------------------------------------------------------------------------
// Stage chunk cc: yb/nb -> buf cc%3, wb -> buf cc&3. Self-ownership for
// yb/nb: thread t stages exactly floats 4t..4t+3 (+1024) that it combines.
// ---------------------------------------------------------------------------
__device__ __forceinline__ void stage_chunk(
    int cc, int t, int i, unsigned sbase,
    const float* __restrict__ y2b,
    const char*  __restrict__ nzb,
    const char*  __restrict__ wgb)
{
    int b3 = cc % 3, b4 = cc & 3;
    unsigned yb_b = sbase + (YB_OFF + b3 * 2048) * 4;
    unsigned nb_b = sbase + (NB_OFF + b3 * 2048) * 4;
    unsigned wb_b = sbase + (WB_OFF + b4 * 2176) * 4;

    #pragma unroll
    for (int g2 = 0; g2 < 2; g2++) {
        int gran = t + g2 * 256;
        cp16(nb_b + gran * 16,
             nzb + ((size_t)(cc * CH + (gran >> 3))) * (LL * 4) + (gran & 7) * 16);
    }
    #pragma unroll
    for (int g2 = 0; g2 < 2; g2++) {
        int gran = t + g2 * 256;
        int oo = gran >> 5, gi = gran & 31;
        cp16(wb_b + oo * (WP2 * 8) + gi * 16,
             wgb + ((size_t)(oo * NN + cc * CH + gi * 2)) * 8);
    }
    #pragma unroll
    for (int q = 0; q < 8; q++) {
        int k = 4 * t + (q & 3) + (q >> 2) * 1024;
        int n  = cc * CH + (k >> 5);
        int j  = k & 31;
        int ch = n / 9;
        int kk = n - ch * 9;
        int ki = kk / 3, kj = kk - ki * 3;
        int rr = i + ki - 1;
        int cl = j + kj - 1;
        int ok = ((unsigned)rr < 32u) & ((unsigned)cl < 32u);
        const float* srcp = ok ? (y2b + (ch * 32 + rr) * 32 + cl) : y2b;
        cp4z(yb_b + k * 4, srcp, ok);
    }
}

// ---------------------------------------------------------------------------
// Fused kernel. Block = (b, image row i). 256 threads:
// h = t>>7 (n-half), r = t&127, o = r>>3, g = r&7, j0 = 4g.
// R8's exact 16-accumulator compute core. ONE barrier per chunk:
//   wait1 -> combine(self-staged) -> stage(c+2) -> commit -> SYNC -> compute
// Races closed by buffer distances (warp skew < 1 iteration between syncs):
//   us mod-3, yb/nb mod-3, wb mod-4.
// ---------------------------------------------------------------------------
__global__ void __launch_bounds__(256, 2) srn_main(
    const float* __restrict__ y2,
    const float* __restrict__ wgt,
    const float* __restrict__ noise,
    float* __restrict__ out)
{
    extern __shared__ float sm[];
    unsigned sbase = (unsigned)__cvta_generic_to_shared(sm);

    int bidx = blockIdx.x;
    int b = bidx >> 5;
    int i = bidx & 31;
    int t = threadIdx.x;
    int h = t >> 7;
    int r = t & 127;
    int o = r >> 3;
    int g = r & 7;
    int j0 = g * 4;

    unsigned long long acc[16];
    #pragma unroll
    for (int k = 0; k < 16; k++) acc[k] = 0ULL;
    float sa1[4] = {0, 0, 0, 0};
    float sa2[4] = {0, 0, 0, 0};

    const float* y2b = y2 + b * (C_ * 32 * 32);
    const char*  nzb = (const char*)(noise + (size_t)b * (NN * LL) + (size_t)i * 32);
    const char*  wgb = (const char*)wgt;

    stage_chunk(0, t, i, sbase, y2b, nzb, wgb);
    CP_COMMIT();
    stage_chunk(1, t, i, sbase, y2b, nzb, wgb);
    CP_COMMIT();

    // builders overlap the in-flight staging DRAM (scratch: US region)
    if (bidx < O_)
        build_A_o(wgt, sm, bidx, t);

    for (int c = 0; c < NCH; c++) {
        int b3 = c % 3;
        CP_WAIT1();                 // stage(c) landed; stage(c+1) may fly

        // ---- combine own staged floats: u = y2part + eps*noise ----
        #pragma unroll
        for (int hf = 0; hf < 2; hf++) {
            int kb = 4 * t + hf * 1024;
            float4 yv = *(const float4*)(sm + YB_OFF + b3 * 2048 + kb);
            float4 nv = *(const float4*)(sm + NB_OFF + b3 * 2048 + kb);
            float v0 = fmaf(EPSN, nv.x, yv.x);
            float v1 = fmaf(EPSN, nv.y, yv.y);
            float v2 = fmaf(EPSN, nv.z, yv.z);
            float v3 = fmaf(EPSN, nv.w, yv.w);
            sa1[0] += v0; sa2[0] += v0 * v0;
            sa1[1] += v1; sa2[1] += v1 * v1;
            sa1[2] += v2; sa2[2] += v2 * v2;
            sa1[3] += v3; sa2[3] += v3 * v3;
            *(float4*)(sm + US_OFF + b3 * 2048 + kb) = make_float4(v0, v1, v2, v3);
        }

        if (c + 2 < NCH)
            stage_chunk(c + 2, t, i, sbase, y2b, nzb, wgb);
        CP_COMMIT();                // exactly one group per iteration
        __syncthreads();            // us[b3] + wb[c&3] visible to all

        // ---- compute over this thread's n-half (R8 core, unchanged) ----
        const float*  up = sm + US_OFF + b3 * 2048 + h * 1024;
        const float2* wp = (const float2*)(sm + WB_OFF) + (c & 3) * 1088 + o * WP2 + h * 32;
        #pragma unroll 4
        for (int nl = 0; nl < 32; nl++) {
            float4 uu = *(const float4*)(up + nl * 32 + j0);
            unsigned long long m1 = *(const unsigned long long*)(wp + nl);
            unsigned long long m2, m3, m4;
            MUL2(m2, m1, m1);
            MUL2(m3, m2, m1);
            MUL2(m4, m2, m2);
            unsigned long long ua = pk2(uu.x, uu.x);
            unsigned long long ub = pk2(uu.y, uu.y);
            unsigned long long uc = pk2(uu.z, uu.z);
            unsigned long long ud = pk2(uu.w, uu.w);
            FMA2(acc[0],  m1, ua); FMA2(acc[1],  m2, ua);
            FMA2(acc[2],  m3, ua); FMA2(acc[3],  m4, ua);
            FMA2(acc[4],  m1, ub); FMA2(acc[5],  m2, ub);
            FMA2(acc[6],  m3, ub); FMA2(acc[7],  m4, ub);
            FMA2(acc[8],  m1, uc); FMA2(acc[9],  m2, uc);
            FMA2(acc[10], m3, uc); FMA2(acc[11], m4, uc);
            FMA2(acc[12], m1, ud); FMA2(acc[13], m2, ud);
            FMA2(acc[14], m3, ud); FMA2(acc[15], m4, ud);
        }
        // no second barrier: us/yb/nb mod-3 and wb mod-4 close all races
        // within the <1-iteration warp-skew window.
    }

    __syncthreads();    // all compute done before overlaying scratch

    // ---- stats partials (P1/P2 overlay US) + acc partials (overlay YB) ----
    {
        int slot = t >> 3;
        #pragma unroll
        for (int q = 0; q < 4; q++) {
            int jq = 4 * (t & 7) + q;
            sm[jq * 33 + slot]        = sa1[q];
            sm[1088 + jq * 33 + slot] = sa2[q];
        }
    }
    if (h == 1) {
        float* base = sm + YB_OFF + r * 34;
        #pragma unroll
        for (int k = 0; k < 16; k++)
            *(unsigned long long*)(base + 2 * k) = acc[k];
    }
    __syncthreads();

    if (t < 32) {
        float a = 0.0f, bb = 0.0f;
        #pragma unroll
        for (int s = 0; s < 32; s++) {
            a  += sm[t * 33 + s];
            bb += sm[1088 + t * 33 + s];
        }
        sm[Z0_OFF + t] = a;
        sm[S2_OFF + t] = bb;
    }
    __syncthreads();

    // ---- epilogue: h==0 threads own (o, j0..j0+3) ----
    if (h == 0) {
        const float* base = sm + YB_OFF + r * 34;
        float wv[4][8];
        #pragma unroll
        for (int loc = 0; loc < 4; loc++)
            #pragma unroll
            for (int pp = 0; pp < 4; pp++) {
                unsigned long long a = acc[loc * 4 + pp];
                int k = loc * 4 + pp;
                wv[loc][2 * pp]     = __uint_as_float((unsigned)a)         + base[2 * k];
                wv[loc][2 * pp + 1] = __uint_as_float((unsigned)(a >> 32)) + base[2 * k + 1];
            }

        while (*((volatile int*)&g_Aflag[o]) == 0) {}
        __threadfence();

        float w0v[4], wAw[4];
        #pragma unroll
        for (int loc = 0; loc < 4; loc++) {
            w0v[loc] = sm[Z0_OFF + j0 + loc];
            wAw[loc] = 0.0f;
        }
        const float* A = g_A + o * 81;
        #pragma unroll
        for (int p = 0; p < 9; p++) {
            float tp[4] = {0.0f, 0.0f, 0.0f, 0.0f};
            #pragma unroll
            for (int q = 0; q < 9; q++) {
                float a = __ldg(&A[p * 9 + q]);
                #pragma unroll
                for (int loc = 0; loc < 4; loc++) {
                    float v = (q == 0) ? w0v[loc] : wv[loc][q - 1];
                    tp[loc] = fmaf(a, v, tp[loc]);
                }
            }
            #pragma unroll
            for (int loc = 0; loc < 4; loc++) {
                float v = (p == 0) ? w0v[loc] : wv[loc][p - 1];
                wAw[loc] = fmaf(tp[loc], v, wAw[loc]);
            }
        }

        float4 res;
        #pragma unroll
        for (int loc = 0; loc < 4; loc++) {
            float S2 = sm[S2_OFF + j0 + loc];
            float z0 = w0v[loc];
            float denom = S2 - z0 * z0 * (1.0f / 576.0f);
            float err = (S2 - wAw[loc]) * (575.0f / 576.0f) / denom;
            ((float*)&res)[loc] = expf(-err);
        }
        *(float4*)(out + ((size_t)(b * 16 + o)) * 1024 + i * 32 + j0) = res;
    }
}

// ---------------------------------------------------------------------------
extern "C" void kernel_launch(void* const* d_in, const int* in_sizes, int n_in,
                              void* d_out, int out_size) {
    const float* y2 = nullptr;
    const float* w  = nullptr;
    const float* nz = nullptr;
    for (int k = 0; k < n_in; k++) {
        if      (in_sizes[k] == 524288)  y2 = (const float*)d_in[k];
        else if (in_sizes[k] == 18432)   w  = (const float*)d_in[k];
        else if (in_sizes[k] == 4718592) nz = (const float*)d_in[k];
    }
    if (!y2 || !w || !nz) {
        y2 = (const float*)d_in[0];
        w  = (const float*)d_in[1];
        nz = (const float*)d_in[2];
    }

    const int smem_bytes = SM_FLOATS * 4;   // 108800 B
    cudaFuncSetAttribute(srn_main, cudaFuncAttributeMaxDynamicSharedMemorySize, smem_bytes);
    srn_main<<<B_ * 32, 256, smem_bytes>>>(y2, w, nz, (float*)d_out);
}

// round 13
// speedup vs baseline: 1.9607x; 1.7683x over previous
#include <cuda_runtime.h>
#include <math.h>
#include <stdint.h>

#define O_   16
#define C_   64
#define NN   576
#define LL   1024
#define B_   8
#define CH   64
#define NCH  9
#define EPSN 1e-4f
#define WP2  68        // float2 pitch per o row in wb

// Persistent scratch (no cudaMalloc). g_A rewritten bit-identically each
// launch; stale flags on graph replay are benign (idempotent writes).
__device__ float g_A[O_ * 81];
__device__ int   g_Aflag[O_];

// ---------------------------------------------------------------------------
#define FMA2(acc_, x_, u_) \
    asm("fma.rn.f32x2 %0, %1, %2, %0;" : "+l"(acc_) : "l"(x_), "l"(u_))
#define MUL2(d_, a_, b_) \
    asm("mul.rn.f32x2 %0, %1, %2;" : "=l"(d_) : "l"(a_), "l"(b_))

__device__ __forceinline__ unsigned long long pk2(float a, float b) {
    unsigned long long r;
    asm("mov.b64 %0, {%1, %2};"
        : "=l"(r) : "r"(__float_as_uint(a)), "r"(__float_as_uint(b)));
    return r;
}
__device__ __forceinline__ void cp16(unsigned dst, const void* src) {
    asm volatile("cp.async.cg.shared.global [%0], [%1], 16;" :: "r"(dst), "l"(src));
}
__device__ __forceinline__ void cp4z(unsigned dst, const void* src, int pred) {
    asm volatile("cp.async.ca.shared.global [%0], [%1], 4, %2;"
                 :: "r"(dst), "l"(src), "r"(pred ? 4 : 0));
}
#define CP_COMMIT() asm volatile("cp.async.commit_group;")
#define CP_WAIT1()  asm volatile("cp.async.wait_group 1;")

// ---------------------------------------------------------------------------
// Blocks 0..15: fp32 symmetric-scaled inverse covariance for channel o.
// EXACT R8 table-based builder (known 127-reg configuration).
// Scratch S = us region (6144 floats; needs ~5740). Runs before first combine.
// ---------------------------------------------------------------------------
__device__ void build_A_block(const float* __restrict__ wgt, float* S, int o, int t) {
    float* sXp   = S;           // 576*9 = 5184
    float* parts = S + 5184;    // 243
    float* Cf    = S + 5440;    // 81
    float* Cm    = S + 5536;    // 171
    float* Dv    = S + 5712;    // 9
    float* fv    = S + 5728;    // 9

    for (int n = t; n < NN; n += 256) {
        float w1 = wgt[(o * NN + n) * 2 + 0];
        float w2 = wgt[(o * NN + n) * 2 + 1];
        float* d = sXp + n * 9;
        d[0] = 1.0f;
        d[1] = w1;        d[2] = w2;
        d[3] = w1 * w1;   d[4] = w2 * w2;
        d[5] = d[3] * w1; d[6] = d[4] * w2;
        d[7] = d[3] * d[3]; d[8] = d[4] * d[4];
    }
    __syncthreads();

    if (t < 243) {
        int pair = t / 3, sl = t - pair * 3;
        int p = pair / 9, q = pair - (pair / 9) * 9;
        float a0 = 0, a1 = 0, a2 = 0, a3 = 0;
        int n0 = sl * 192;
        for (int n = n0; n < n0 + 192; n += 4) {
            a0 += sXp[n * 9 + p]       * sXp[n * 9 + q];
            a1 += sXp[(n + 1) * 9 + p] * sXp[(n + 1) * 9 + q];
            a2 += sXp[(n + 2) * 9 + p] * sXp[(n + 2) * 9 + q];
            a3 += sXp[(n + 3) * 9 + p] * sXp[(n + 3) * 9 + q];
        }
        parts[t] = (a0 + a1) + (a2 + a3);
    }
    __syncthreads();
    if (t < 81) Cf[t] = parts[t * 3] + parts[t * 3 + 1] + parts[t * 3 + 2];
    __syncthreads();
    if (t < 9) Dv[t] = rsqrtf(Cf[t * 9 + t]);
    __syncthreads();
    if (t < 81) {
        int p = t / 9, q = t - 9 * (t / 9);
        Cm[p * 19 + q]     = Cf[t] * Dv[p] * Dv[q];
        Cm[p * 19 + 9 + q] = (p == q) ? 1.0f : 0.0f;
    }
    __syncthreads();

    for (int k = 0; k < 9; k++) {
        if (t < 9) fv[t] = Cm[t * 19 + k];
        __syncthreads();
        if (t < 19) Cm[k * 19 + t] *= (1.0f / fv[k]);
        __syncthreads();
        if (t < 171) {
            int ii = t / 19, jj = t - 19 * (t / 19);
            if (ii != k) Cm[ii * 19 + jj] -= fv[ii] * Cm[k * 19 + jj];
        }
        __syncthreads();
    }
    if (t < 81) {
        int p = t / 9, q = t - 9 * (t / 9);
        g_A[o * 81 + t] = Dv[p] * Cm[p * 19 + 9 + q] * Dv[q];
        __threadfence();
    }
    __syncthreads();
    if (t == 0) *((volatile int*)&g_Aflag[o]) = 1;
    __syncthreads();
}

// ---------------------------------------------------------------------------
// Stage chunk cc: yb/nb cycle mod 3 (consumed pre-barrier by self-staging
// threads), wb mod 4 (consumed post-barrier). Identical to R8 except wb mod.
// ---------------------------------------------------------------------------
__device__ __forceinline__ void stage_chunk(
    int cc, int t, int i,
    unsigned yb_b, unsigned nb_b, unsigned wb_b,
    const float* __restrict__ y2b,
    const char*  __restrict__ nzb,
    const char*  __restrict__ wgb)
{
    int bi = cc % 3;
    int b4 = cc & 3;
    // noise: 16B granules t and t+256
    #pragma unroll
    for (int g2 = 0; g2 < 2; g2++) {
        int gran = t + g2 * 256;
        int nl = gran >> 3;
        cp16(nb_b + bi * 8192 + gran * 16,
             nzb + ((size_t)(cc * CH + nl)) * (LL * 4) + (gran & 7) * 16);
    }
    // weights: [o][32 granules] -> wb[b4][o][gi], pitch WP2 float2
    #pragma unroll
    for (int g2 = 0; g2 < 2; g2++) {
        int gran = t + g2 * 256;
        int oo = gran >> 5;
        int gi = gran & 31;
        cp16(wb_b + b4 * 8704 + oo * (WP2 * 8) + gi * 16,
             wgb + ((size_t)(oo * NN + cc * CH + gi * 2)) * 8);
    }
    // y2 unfold: 4B zfill at floats 4t+q (+1024)
    #pragma unroll
    for (int q = 0; q < 8; q++) {
        int k = 4 * t + (q & 3) + (q >> 2) * 1024;
        int n  = cc * CH + (k >> 5);
        int j  = k & 31;
        int ch = n / 9;
        int kk = n - ch * 9;
        int ki = kk / 3, kj = kk - ki * 3;
        int rr = i + ki - 1;
        int cl = j + kj - 1;
        int ok = ((unsigned)rr < 32u) & ((unsigned)cl < 32u);
        const float* srcp = ok ? (y2b + (ch * 32 + rr) * 32 + cl) : y2b;
        cp4z(yb_b + bi * 8192 + k * 4, srcp, ok);
    }
}

// ---------------------------------------------------------------------------
// Fused kernel (R8 core). Block = (b, image row i). 256 threads:
// h = t>>7 (n-half), r = t&127, o = r>>3, g = r&7, j0 = 4g.
// smem (floats): us[3][2048]@0, yb[3][2048]@6144, nb[3][2048]@12288,
// wb[4][2176]@18432, z0s@27136, s2s@27168. Total 27200 fl = 108800 B.
// ONE barrier per chunk (trailing sync removed; wb widened mod-4).
// ---------------------------------------------------------------------------
__global__ void __launch_bounds__(256, 2) srn_main(
    const float* __restrict__ y2,
    const float* __restrict__ wgt,
    const float* __restrict__ noise,
    float* __restrict__ out)
{
    extern __shared__ float sm[];
    float*  us  = sm;                     // 3 x 2048
    float*  yb  = sm + 6144;              // 3 x 2048 (stats scratch after loop)
    float*  nb  = sm + 12288;             // 3 x 2048 (acc scratch after loop)
    float2* wb  = (float2*)(sm + 18432);  // 4 x 1088 float2
    float*  z0s = sm + 27136;
    float*  s2s = sm + 27168;

    unsigned sbase = (unsigned)__cvta_generic_to_shared(sm);
    const unsigned yb_b = sbase + 6144 * 4;
    const unsigned nb_b = sbase + 12288 * 4;
    const unsigned wb_b = sbase + 18432 * 4;

    int b = blockIdx.x >> 5;
    int i = blockIdx.x & 31;
    int t = threadIdx.x;
    int h = t >> 7;
    int r = t & 127;
    int o = r >> 3;
    int g = r & 7;
    int j0 = g * 4;

    unsigned long long acc[16];
    #pragma unroll
    for (int k = 0; k < 16; k++) acc[k] = 0ULL;
    float sa1[4] = {0, 0, 0, 0};
    float sa2[4] = {0, 0, 0, 0};

    const float* y2b = y2 + b * (C_ * 32 * 32);
    const char*  nzb = (const char*)(noise + (size_t)b * (NN * LL) + (size_t)i * 32);
    const char*  wgb = (const char*)wgt;

    stage_chunk(0, t, i, yb_b, nb_b, wb_b, y2b, nzb, wgb);
    CP_COMMIT();
    stage_chunk(1, t, i, yb_b, nb_b, wb_b, y2b, nzb, wgb);
    CP_COMMIT();

    // blocks 0..15: build the 9x9 inverse covariance (overlaps staging DRAM)
    if (blockIdx.x < O_)
        build_A_block(wgt, us, blockIdx.x, t);

    for (int c = 0; c < NCH; c++) {
        int bi = c % 3;
        CP_WAIT1();                 // stage(c) landed (c+1 may be in flight)

        // ---- combine own staged floats: u = y2part + eps*noise ----
        #pragma unroll
        for (int hf = 0; hf < 2; hf++) {
            int kb = 4 * t + hf * 1024;
            float4 yv = *(const float4*)(yb + bi * 2048 + kb);
            float4 nv = *(const float4*)(nb + bi * 2048 + kb);
            float v0 = fmaf(EPSN, nv.x, yv.x);
            float v1 = fmaf(EPSN, nv.y, yv.y);
            float v2 = fmaf(EPSN, nv.z, yv.z);
            float v3 = fmaf(EPSN, nv.w, yv.w);
            sa1[0] += v0; sa2[0] += v0 * v0;
            sa1[1] += v1; sa2[1] += v1 * v1;
            sa1[2] += v2; sa2[2] += v2 * v2;
            sa1[3] += v3; sa2[3] += v3 * v3;
            *(float4*)(us + bi * 2048 + kb) = make_float4(v0, v1, v2, v3);
        }

        if (c + 2 < NCH)
            stage_chunk(c + 2, t, i, yb_b, nb_b, wb_b, y2b, nzb, wgb);
        CP_COMMIT();                // one group per iteration (may be empty)
        __syncthreads();            // us[bi] + wb[c&3] visible to all

        // ---- compute over this thread's n-half (32 n) ----
        const float*  up = us + bi * 2048 + h * 32 * 32;
        const float2* wp = wb + (c & 3) * (O_ * WP2) + o * WP2 + h * 32;
        #pragma unroll 4
        for (int nl = 0; nl < 32; nl++) {
            float4 uu = *(const float4*)(up + nl * 32 + j0);
            unsigned long long m1 = *(const unsigned long long*)(wp + nl);
            unsigned long long m2, m3, m4;
            MUL2(m2, m1, m1);
            MUL2(m3, m2, m1);
            MUL2(m4, m2, m2);
            unsigned long long ua = pk2(uu.x, uu.x);
            unsigned long long ub = pk2(uu.y, uu.y);
            unsigned long long uc = pk2(uu.z, uu.z);
            unsigned long long ud = pk2(uu.w, uu.w);
            FMA2(acc[0],  m1, ua); FMA2(acc[1],  m2, ua);
            FMA2(acc[2],  m3, ua); FMA2(acc[3],  m4, ua);
            FMA2(acc[4],  m1, ub); FMA2(acc[5],  m2, ub);
            FMA2(acc[6],  m3, ub); FMA2(acc[7],  m4, ub);
            FMA2(acc[8],  m1, uc); FMA2(acc[9],  m2, uc);
            FMA2(acc[10], m3, uc); FMA2(acc[11], m4, uc);
            FMA2(acc[12], m1, ud); FMA2(acc[13], m2, ud);
            FMA2(acc[14], m3, ud); FMA2(acc[15], m4, ud);
        }
        // no trailing barrier: us/yb/nb mod-3 and wb mod-4 close all races
        // within the <1-iteration warp-skew window between chunk barriers.
    }

    __syncthreads();    // all compute done before overlaying scratch

    // ---- stats partials (stride 33, yb) + acc partials (stride 33, nb) ----
    {
        int slot = t >> 3;
        #pragma unroll
        for (int q = 0; q < 4; q++) {
            int jq = 4 * (t & 7) + q;
            yb[jq * 33 + slot]        = sa1[q];
            yb[1066 + jq * 33 + slot] = sa2[q];
        }
    }
    if (h == 1) {
        #pragma unroll
        for (int k = 0; k < 16; k++) {
            nb[r * 33 + 2 * k]     = __uint_as_float((unsigned)acc[k]);
            nb[r * 33 + 2 * k + 1] = __uint_as_float((unsigned)(acc[k] >> 32));
        }
    }
    __syncthreads();

    if (t < 32) {
        float a = 0.0f, bb = 0.0f;
        #pragma unroll
        for (int s = 0; s < 32; s++) {
            a  += yb[t * 33 + s];
            bb += yb[1066 + t * 33 + s];
        }
        z0s[t] = a;
        s2s[t] = bb;
    }
    __syncthreads();

    if (h == 0) {
        float wv[4][8];
        #pragma unroll
        for (int loc = 0; loc < 4; loc++)
            #pragma unroll
            for (int pp = 0; pp < 4; pp++) {
                unsigned long long a = acc[loc * 4 + pp];
                int k = loc * 4 + pp;
                wv[loc][2 * pp]     = __uint_as_float((unsigned)a)         + nb[r * 33 + 2 * k];
                wv[loc][2 * pp + 1] = __uint_as_float((unsigned)(a >> 32)) + nb[r * 33 + 2 * k + 1];
            }

        // wait for this o's inverse covariance (normally long done)
        {
            volatile int* fl = g_Aflag + o;
            while (*fl == 0) {}
        }
        __threadfence();

        float w0v[4], wAw[4];
        #pragma unroll
        for (int loc = 0; loc < 4; loc++) {
            w0v[loc] = z0s[j0 + loc];
            wAw[loc] = 0.0f;
        }
        const float* A = g_A + o * 81;
        #pragma unroll
        for (int p = 0; p < 9; p++) {
            float tp[4] = {0.0f, 0.0f, 0.0f, 0.0f};
            #pragma unroll
            for (int q = 0; q < 9; q++) {
                float a = A[p * 9 + q];
                #pragma unroll
                for (int loc = 0; loc < 4; loc++) {
                    float v = (q == 0) ? w0v[loc] : wv[loc][q - 1];
                    tp[loc] = fmaf(a, v, tp[loc]);
                }
            }
            #pragma unroll
            for (int loc = 0; loc < 4; loc++) {
                float v = (p == 0) ? w0v[loc] : wv[loc][p - 1];
                wAw[loc] = fmaf(tp[loc], v, wAw[loc]);
            }
        }

        float4 res;
        #pragma unroll
        for (int loc = 0; loc < 4; loc++) {
            float S2 = s2s[j0 + loc];
            float z0 = w0v[loc];
            float denom = S2 - z0 * z0 * (1.0f / 576.0f);
            float err = (S2 - wAw[loc]) * (575.0f / 576.0f) / denom;
            ((float*)&res)[loc] = expf(-err);
        }
        *(float4*)(out + ((size_t)(b * 16 + o)) * 1024 + i * 32 + j0) = res;
    }
}

// ---------------------------------------------------------------------------
extern "C" void kernel_launch(void* const* d_in, const int* in_sizes, int n_in,
                              void* d_out, int out_size) {
    const float* y2 = nullptr;
    const float* w  = nullptr;
    const float* nz = nullptr;
    for (int k = 0; k < n_in; k++) {
        if      (in_sizes[k] == 524288)  y2 = (const float*)d_in[k];
        else if (in_sizes[k] == 18432)   w  = (const float*)d_in[k];
        else if (in_sizes[k] == 4718592) nz = (const float*)d_in[k];
    }
    if (!y2 || !w || !nz) {
        y2 = (const float*)d_in[0];
        w  = (const float*)d_in[1];
        nz = (const float*)d_in[2];
    }

    const int smem_bytes = 27200 * 4;   // 108800 B
    cudaFuncSetAttribute(srn_main, cudaFuncAttributeMaxDynamicSharedMemorySize, smem_bytes);
    srn_main<<<B_ * 32, 256, smem_bytes>>>(y2, w, nz, (float*)d_out);
}